// round 1
// baseline (speedup 1.0000x reference)
#include <cuda_runtime.h>
#include <cuda_bf16.h>
#include <cstdint>

// ---------------------------------------------------------------------------
// Scratch (device globals -- no runtime allocation allowed)
// ---------------------------------------------------------------------------
__device__ float g_conv1[64 * 64 * 56 * 56];   // conv1 output (relu'd)  ~51.4MB
__device__ float g_part[4 * 64 * 256];         // conv2 partial pooled sums [rt][n][oc]
__device__ float g_mu[64 * 32];
__device__ float g_kappa[64];
__device__ float g_z[64 * 32];

// ---------------------------------------------------------------------------
// Kernel 1: conv1 7x7 stride4 pad3, 6->64 ch, + bias + relu
// tile: 64 oc x 56 cols x 4 rows per block. thread: 8 oc x 8 cols.
// ---------------------------------------------------------------------------
#define XR1 233   // padded smem row stride (4*233 % 32 = 4 -> conflict-free rows)

__global__ __launch_bounds__(224, 2)
void conv1_kernel(const float* __restrict__ x, const float* __restrict__ W1,
                  const float* __restrict__ b1) {
    __shared__ float ws[49 * 64];       // [q][oc]
    __shared__ float xs[19 * XR1];      // one ci, 19 input rows x 227 cols (padded)

    const int rt  = blockIdx.x;         // 0..13 (4 output rows each)
    const int n   = blockIdx.y;         // batch
    const int tid = threadIdx.x;        // 224 threads
    const int og  = tid & 7;            // oc group (8 oc each)
    const int row = (tid >> 3) & 3;     // output row within tile
    const int cg  = tid >> 5;           // col group (8 cols each), 0..6

    float acc[8][8];
#pragma unroll
    for (int o = 0; o < 8; o++)
#pragma unroll
        for (int p = 0; p < 8; p++) acc[o][p] = 0.f;

    for (int ci = 0; ci < 6; ci++) {
        __syncthreads();
        // weights for this ci: W1[oc][ci][7][7] -> ws[q*64+oc]
        for (int i = tid; i < 3136; i += 224) {
            int oc = i / 49, q = i - oc * 49;
            ws[q * 64 + oc] = W1[oc * 294 + ci * 49 + q];
        }
        // input tile: rows ih = rt*16-3 .. rt*16+15, cols iw = -3..223
        const float* xb = x + ((size_t)(n * 6 + ci)) * 224 * 224;
        for (int i = tid; i < 19 * 227; i += 224) {
            int r = i / 227, c = i - r * 227;
            int ih = rt * 16 - 3 + r;
            int iw = c - 3;
            float v = 0.f;
            if (ih >= 0 && ih < 224 && iw >= 0) v = xb[ih * 224 + iw];
            xs[r * XR1 + c] = v;
        }
        __syncthreads();

        for (int kh = 0; kh < 7; kh++) {
            const float* xrow = &xs[(row * 4 + kh) * XR1 + cg * 32];
#pragma unroll
            for (int kw = 0; kw < 7; kw++) {
                const int q = kh * 7 + kw;
                const float4 wa = *(const float4*)&ws[q * 64 + og * 8];
                const float4 wb = *(const float4*)&ws[q * 64 + og * 8 + 4];
                float xin[8];
#pragma unroll
                for (int p = 0; p < 8; p++) xin[p] = xrow[p * 4 + kw];
#pragma unroll
                for (int p = 0; p < 8; p++) {
                    acc[0][p] += wa.x * xin[p];
                    acc[1][p] += wa.y * xin[p];
                    acc[2][p] += wa.z * xin[p];
                    acc[3][p] += wa.w * xin[p];
                    acc[4][p] += wb.x * xin[p];
                    acc[5][p] += wb.y * xin[p];
                    acc[6][p] += wb.z * xin[p];
                    acc[7][p] += wb.w * xin[p];
                }
            }
        }
    }

    const int oh = rt * 4 + row;
#pragma unroll
    for (int o = 0; o < 8; o++) {
        const int oc = og * 8 + o;
        const float bv = b1[oc];
        float* outp = &g_conv1[(((size_t)n * 64 + oc) * 56 + oh) * 56 + cg * 8];
#pragma unroll
        for (int p = 0; p < 8; p += 4) {
            float4 v;
            v.x = fmaxf(acc[o][p + 0] + bv, 0.f);
            v.y = fmaxf(acc[o][p + 1] + bv, 0.f);
            v.z = fmaxf(acc[o][p + 2] + bv, 0.f);
            v.w = fmaxf(acc[o][p + 3] + bv, 0.f);
            *(float4*)&outp[p] = v;
        }
    }
}

// ---------------------------------------------------------------------------
// Kernel 2: conv2 3x3 stride2 pad1, 64->256 ch, + bias + relu + pooled sums
// (conv2 activations never hit HBM; deterministic per-block partial sums)
// tile: 64 oc x 28 cols x 8 rows. thread: 8 oc x 4 cols x 2 rows.
// ---------------------------------------------------------------------------
#define XR2 59    // padded (4*59 % 32 = 12 -> conflict-free across rowg)
#define CK  4     // ci chunk

__global__ __launch_bounds__(224, 2)
void conv2_kernel(const float* __restrict__ W2, const float* __restrict__ b2) {
    __shared__ float ws[CK * 9 * 64];       // [ci_l][q][oc]
    __shared__ float xs[CK * 17 * XR2];     // [ci_l][r][c]
    __shared__ float red[224 * 8];

    const int rt  = blockIdx.x;   // 0..3 (8 output rows; last tile only 4 valid)
    const int ot  = blockIdx.y;   // 0..3 oc tile of 64
    const int n   = blockIdx.z;
    const int tid = threadIdx.x;
    const int og   = tid & 7;
    const int rowg = (tid >> 3) & 3;
    const int colg = tid >> 5;    // 0..6 (one per warp)

    float acc[8][8];  // [o][rr*4+pc]
#pragma unroll
    for (int o = 0; o < 8; o++)
#pragma unroll
        for (int p = 0; p < 8; p++) acc[o][p] = 0.f;

    for (int cc = 0; cc < 64 / CK; cc++) {
        __syncthreads();
        for (int i = tid; i < CK * 9 * 64; i += 224) {
            int oc = i / (CK * 9), rsd = i - oc * (CK * 9);
            int cil = rsd / 9, q = rsd - cil * 9;
            ws[(cil * 9 + q) * 64 + oc] =
                W2[(((size_t)(ot * 64 + oc)) * 64 + (cc * CK + cil)) * 9 + q];
        }
        for (int i = tid; i < CK * 17 * 57; i += 224) {
            int cil = i / (17 * 57);
            int rsd = i - cil * (17 * 57);
            int r = rsd / 57, c = rsd - r * 57;
            int ih = rt * 16 - 1 + r;
            int iw = c - 1;
            float v = 0.f;
            if (ih >= 0 && ih < 56 && iw >= 0 && iw < 56)
                v = g_conv1[(((size_t)n * 64 + (cc * CK + cil)) * 56 + ih) * 56 + iw];
            xs[(cil * 17 + r) * XR2 + c] = v;
        }
        __syncthreads();

#pragma unroll
        for (int cil = 0; cil < CK; cil++) {
#pragma unroll
            for (int kh = 0; kh < 3; kh++) {
#pragma unroll
                for (int kw = 0; kw < 3; kw++) {
                    const int q = kh * 3 + kw;
                    const float4 wa = *(const float4*)&ws[(cil * 9 + q) * 64 + og * 8];
                    const float4 wb = *(const float4*)&ws[(cil * 9 + q) * 64 + og * 8 + 4];
                    float xin[8];
#pragma unroll
                    for (int rr = 0; rr < 2; rr++)
#pragma unroll
                        for (int pc = 0; pc < 4; pc++)
                            xin[rr * 4 + pc] =
                                xs[(cil * 17 + (rowg * 2 + rr) * 2 + kh) * XR2 +
                                   (colg * 4 + pc) * 2 + kw];
#pragma unroll
                    for (int p = 0; p < 8; p++) {
                        acc[0][p] += wa.x * xin[p];
                        acc[1][p] += wa.y * xin[p];
                        acc[2][p] += wa.z * xin[p];
                        acc[3][p] += wa.w * xin[p];
                        acc[4][p] += wb.x * xin[p];
                        acc[5][p] += wb.y * xin[p];
                        acc[6][p] += wb.z * xin[p];
                        acc[7][p] += wb.w * xin[p];
                    }
                }
            }
        }
    }

    // bias + relu + per-thread pooled sums over VALID rows only
    const int oh0 = rt * 8 + rowg * 2;
    float s[8];
#pragma unroll
    for (int o = 0; o < 8; o++) {
        const float bv = b2[ot * 64 + og * 8 + o];
        float t = 0.f;
#pragma unroll
        for (int rr = 0; rr < 2; rr++) {
            if (oh0 + rr < 28) {
#pragma unroll
                for (int pc = 0; pc < 4; pc++)
                    t += fmaxf(acc[o][rr * 4 + pc] + bv, 0.f);
            }
        }
        s[o] = t;
    }
#pragma unroll
    for (int o = 0; o < 8; o++) red[tid * 8 + o] = s[o];
    __syncthreads();
    // deterministic tree: thread oc_l sums the 28 threads with matching og
    if (tid < 64) {
        const int o = tid & 7, ogr = tid >> 3;
        float t = 0.f;
        for (int k = 0; k < 28; k++) t += red[(ogr + 8 * k) * 8 + o];
        g_part[((size_t)rt * 64 + n) * 256 + ot * 64 + tid] = t;
    }
}

// ---------------------------------------------------------------------------
// Kernel 3: mean-pool finish + fc(256->512) + mu head (normalize) + kappa head
// one block per batch element, 512 threads
// ---------------------------------------------------------------------------
__global__ void head_kernel(const float* __restrict__ Wh, const float* __restrict__ bh,
                            const float* __restrict__ Wmu, const float* __restrict__ bmu,
                            const float* __restrict__ Wk, const float* __restrict__ bk,
                            float* __restrict__ d_out, int out_size) {
    __shared__ float p[256];
    __shared__ float hs[512];
    __shared__ float ms[32];
    __shared__ float kap;

    const int b = blockIdx.x, t = threadIdx.x;

    if (t < 256) {
        float s = 0.f;
        for (int rt = 0; rt < 4; rt++) s += g_part[((size_t)rt * 64 + b) * 256 + t];
        p[t] = s / 784.0f;
    }
    __syncthreads();

    float hv = bh[t];
    for (int k = 0; k < 256; k++) hv += p[k] * Wh[k * 512 + t];
    hs[t] = hv;
    __syncthreads();

    if (t < 32) {
        float m = bmu[t];
        for (int k = 0; k < 512; k++) m += hs[k] * Wmu[k * 32 + t];
        ms[t] = m;
    }
    if (t >= 32 && t < 64) {
        float s2 = 0.f;
        for (int k = t - 32; k < 512; k += 32) s2 += hs[k] * Wk[k];
        for (int off = 16; off; off >>= 1) s2 += __shfl_down_sync(0xffffffffu, s2, off);
        if (t == 32) {
            float xk = s2 + bk[0];
            float sp = fmaxf(xk, 0.f) + log1pf(expf(-fabsf(xk)));   // jax softplus
            kap = sp + 1.0f;
        }
    }
    __syncthreads();

    if (t < 32) {
        float m = ms[t];
        float ss = m * m;
        for (int off = 16; off; off >>= 1) ss += __shfl_xor_sync(0xffffffffu, ss, off);
        float nrm = sqrtf(fmaxf(ss, 1e-24f));
        float muv = m / nrm;
        g_mu[b * 32 + t] = muv;
        if (out_size >= 2560) d_out[448 + b * 32 + t] = muv;
    }
    if (t == 0) {
        g_kappa[b] = kap;
        if (out_size >= 2560) d_out[448 + 2048 + b] = kap;
    }
}

// ---------------------------------------------------------------------------
// Threefry-2x32 (JAX/XLA exact), partitionable semantics
// ---------------------------------------------------------------------------
__device__ __forceinline__ uint32_t rotl32(uint32_t x, int d) {
    return (x << d) | (x >> (32 - d));
}

__device__ void threefry2x32(uint32_t k0, uint32_t k1, uint32_t c0, uint32_t c1,
                             uint32_t& o0, uint32_t& o1) {
    uint32_t ks2 = k0 ^ k1 ^ 0x1BD11BDAu;
    uint32_t x0 = c0 + k0, x1 = c1 + k1;
#define TF_RND(R) { x0 += x1; x1 = rotl32(x1, R); x1 ^= x0; }
    TF_RND(13) TF_RND(15) TF_RND(26) TF_RND(6)
    x0 += k1;  x1 += ks2 + 1u;
    TF_RND(17) TF_RND(29) TF_RND(16) TF_RND(24)
    x0 += ks2; x1 += k0 + 2u;
    TF_RND(13) TF_RND(15) TF_RND(26) TF_RND(6)
    x0 += k0;  x1 += k1 + 3u;
    TF_RND(17) TF_RND(29) TF_RND(16) TF_RND(24)
    x0 += k1;  x1 += ks2 + 4u;
    TF_RND(13) TF_RND(15) TF_RND(26) TF_RND(6)
    x0 += ks2; x1 += k0 + 5u;
#undef TF_RND
    o0 = x0; o1 = x1;
}

// partitionable 32-bit random_bits for flat index i (hi word = 0 here)
__device__ __forceinline__ uint32_t tf_bits32(uint32_t k0, uint32_t k1, uint32_t idx) {
    uint32_t a, b;
    threefry2x32(k0, k1, 0u, idx, a, b);
    return a ^ b;
}

__device__ __forceinline__ float bits_to_unit(uint32_t bits) {
    return __uint_as_float((bits >> 9) | 0x3f800000u) - 1.0f;   // [0,1)
}

// XLA ErfInv32 polynomial (exact coefficients from xla math.cc)
__device__ float erfinv_xla(float x) {
    float w = -log1pf(-x * x);
    float p;
    if (w < 5.0f) {
        w = w - 2.5f;
        p = 2.81022636e-08f;
        p = 3.43273939e-07f + p * w;
        p = -3.5233877e-06f + p * w;
        p = -4.39150654e-06f + p * w;
        p = 0.00021858087f + p * w;
        p = -0.00125372503f + p * w;
        p = -0.00417768164f + p * w;
        p = 0.246640727f + p * w;
        p = 1.50140941f + p * w;
    } else {
        w = sqrtf(w) - 3.0f;
        p = -0.000200214257f;
        p = 0.000100950558f + p * w;
        p = 0.00134934322f + p * w;
        p = -0.00367342844f + p * w;
        p = 0.00573950773f + p * w;
        p = -0.0076224613f + p * w;
        p = 0.00943887047f + p * w;
        p = 1.00167406f + p * w;
        p = 2.83297682f + p * w;
    }
    return p * x;
}

// ---------------------------------------------------------------------------
// Kernel 4: vMF Wood sampling, 1 block x 64 threads (one per batch element)
// ---------------------------------------------------------------------------
__global__ void sample_kernel() {
    const int b = threadIdx.x;   // 0..63

    // key(42) -> data (0,42); fold-like split: k_w=tf(key,(0,0)), k_v=tf(key,(0,1))
    uint32_t kw0, kw1, kv0, kv1;
    threefry2x32(0u, 42u, 0u, 0u, kw0, kw1);
    threefry2x32(0u, 42u, 0u, 1u, kv0, kv1);

    const float kappa = g_kappa[b];
    float w = 0.f;
    bool accd = false;

    for (int i = 0; i < 10; i++) {
        uint32_t f0, f1;
        // k1 = fold_in(k_w, 2i)
        threefry2x32(kw0, kw1, 0u, (uint32_t)(2 * i), f0, f1);
        float u1 = bits_to_unit(tf_bits32(f0, f1, (uint32_t)b));
        float wc = 2.0f * u1 - 1.0f;
        // k2 = fold_in(k_w, 2i+1)
        threefry2x32(kw0, kw1, 0u, (uint32_t)(2 * i + 1), f0, f1);
        float u2 = bits_to_unit(tf_bits32(f0, f1, (uint32_t)b));

        float one_m = fmaxf(1.0f - wc * wc, 1e-40f);
        float log_p = kappa * wc + 14.5f * logf(one_m);  // 0.5*(31-2)=14.5
        float log_r = logf(u2 + 1e-40f);
        bool newly = (log_r + kappa <= log_p) && !accd;
        if (newly) { w = wc; accd = true; }
    }
    w = fminf(fmaxf(w, -1.0f), 1.0f);

    // tangent direction: normal(k_v, (64,31)), row b, then normalize
    const float LOv = -0.99999994f;  // nextafter(-1,0)
    float v[31];
    float ss = 0.f;
#pragma unroll
    for (int t = 0; t < 31; t++) {
        uint32_t idx = (uint32_t)(b * 31 + t);
        float f = bits_to_unit(tf_bits32(kv0, kv1, idx));
        float u = fmaxf(LOv, f * 2.0f + LOv);
        float nv = 1.41421354f * erfinv_xla(u);
        v[t] = nv;
        ss += nv * nv;
    }
    float rn = sqrtf(fmaxf(ss, 1e-24f));

    float sq = sqrtf(fmaxf(1.0f - w * w, 1e-40f));
    float zt[32];
#pragma unroll
    for (int t = 0; t < 31; t++) zt[t] = sq * (v[t] / rn);
    zt[31] = w;

    // Householder reflection: u = normalize(e_d - mu); z = zt - 2 (zt.u) u
    float uh[32];
    float ss2 = 0.f;
#pragma unroll
    for (int i = 0; i < 32; i++) {
        float e = ((i == 31) ? 1.0f : 0.0f) - g_mu[b * 32 + i];
        uh[i] = e;
        ss2 += e * e;
    }
    float nn = sqrtf(fmaxf(ss2, 1e-24f));
    float dot = 0.f;
#pragma unroll
    for (int i = 0; i < 32; i++) { uh[i] = uh[i] / nn; dot += zt[i] * uh[i]; }
#pragma unroll
    for (int i = 0; i < 32; i++) g_z[b * 32 + i] = zt[i] - 2.0f * dot * uh[i];
}

// ---------------------------------------------------------------------------
// Kernel 5: ResNetMLP head 32->512->512->32->7, one block per batch element
// ---------------------------------------------------------------------------
__global__ void mlp_kernel(const float* __restrict__ M1, const float* __restrict__ bM1,
                           const float* __restrict__ M2, const float* __restrict__ bM2,
                           const float* __restrict__ M3, const float* __restrict__ bM3,
                           const float* __restrict__ M4, const float* __restrict__ bM4,
                           float* __restrict__ d_out) {
    __shared__ float zs[32];
    __shared__ float a1[512];
    __shared__ float a2[512];
    __shared__ float a3[32];
    const int b = blockIdx.x, t = threadIdx.x;

    if (t < 32) zs[t] = g_z[b * 32 + t];
    __syncthreads();

    float y = bM1[t];
    for (int k = 0; k < 32; k++) y += zs[k] * M1[k * 512 + t];
    a1[t] = fmaxf(y, 0.f);
    __syncthreads();

    y = bM2[t];
    for (int k = 0; k < 512; k++) y += a1[k] * M2[k * 512 + t];
    a2[t] = fmaxf(y, 0.f);
    __syncthreads();

    if (t < 32) {
        y = bM3[t];
        for (int k = 0; k < 512; k++) y += a2[k] * M3[k * 32 + t];
        a3[t] = fmaxf(y, 0.f);
    }
    __syncthreads();

    if (t < 7) {
        y = bM4[t];
        for (int k = 0; k < 32; k++) y += a3[k] * M4[k * 7 + t];
        d_out[b * 7 + t] = y;
    }
}

// ---------------------------------------------------------------------------
// Launch
// ---------------------------------------------------------------------------
extern "C" void kernel_launch(void* const* d_in, const int* in_sizes, int n_in,
                              void* d_out, int out_size) {
    const float* x   = (const float*)d_in[0];
    const float* W1  = (const float*)d_in[1];
    const float* b1  = (const float*)d_in[2];
    const float* W2  = (const float*)d_in[3];
    const float* b2  = (const float*)d_in[4];
    const float* Wh  = (const float*)d_in[5];
    const float* bh  = (const float*)d_in[6];
    const float* Wmu = (const float*)d_in[7];
    const float* bmu = (const float*)d_in[8];
    const float* Wk  = (const float*)d_in[9];
    const float* bk  = (const float*)d_in[10];
    const float* M1  = (const float*)d_in[11];
    const float* bM1 = (const float*)d_in[12];
    const float* M2  = (const float*)d_in[13];
    const float* bM2 = (const float*)d_in[14];
    const float* M3  = (const float*)d_in[15];
    const float* bM3 = (const float*)d_in[16];
    const float* M4  = (const float*)d_in[17];
    const float* bM4 = (const float*)d_in[18];
    float* out = (float*)d_out;

    conv1_kernel<<<dim3(14, 64), 224>>>(x, W1, b1);
    conv2_kernel<<<dim3(4, 4, 64), 224>>>(W2, b2);
    head_kernel<<<64, 512>>>(Wh, bh, Wmu, bmu, Wk, bk, out, out_size);
    sample_kernel<<<1, 64>>>();
    mlp_kernel<<<64, 512>>>(M1, bM1, M2, bM2, M3, bM3, M4, bM4, out);
}